// round 14
// baseline (speedup 1.0000x reference)
#include <cuda_runtime.h>
#include <math.h>

#define B_N 1024
#define F_N 257
#define BF_N (B_N * F_N)
#define T_CORE 65
#define NBX 4
#define NPART (NBX * B_N)   // 4096
#define NTH 288             // 9 warps

typedef unsigned long long u64;

// -------- device scratch (allocation-free) --------
__device__ __align__(16) float g_h[2][(size_t)BF_N * 32];
__device__ __align__(16) float g_c[2][(size_t)BF_N * 32];   // ping-pong per layer
__device__ __align__(16) float g_part[64][NPART];           // [kind*32+ch][block]
__device__ __align__(16) float g_bn[2][32];

__device__ __forceinline__ float gelu_f(float x) {
    return 0.5f * x * (1.0f + erff(x * 0.70710678118654752440f));
}
__device__ __forceinline__ void ffma2(u64& d, u64 a, u64 b) {
    asm("fma.rn.f32x2 %0, %1, %2, %0;" : "+l"(d) : "l"(a), "l"(b));
}
__device__ __forceinline__ u64 pack2(float x) {
    u64 r; asm("mov.b64 %0, {%1, %1};" : "=l"(r) : "f"(x)); return r;
}
__device__ __forceinline__ float2 unpack2(u64 a) {
    float2 f; asm("mov.b64 {%0, %1}, %2;" : "=f"(f.x), "=f"(f.y) : "l"(a)); return f;
}

// ===== conv (width-3 over F) on smem y + BN partials; ALL NTH threads call =====
// Token-PAIR per thread; weights read once per pair via 16B LDS; zero-padded rows.
__device__ __forceinline__ void conv_phase(const float* y, const float* cws,
                                           int fb, int E, size_t rowbase,
                                           int pidx, float* red, float* gc_out) {
    int tid = threadIdx.x;
    int pr = tid >> 2, o0 = (tid & 3) << 3;
    int tA = pr * 2;
    float s1[8], s2[8];
#pragma unroll
    for (int j = 0; j < 8; j++) { s1[j] = 0.f; s2[j] = 0.f; }
    if (tA < E) {
        bool vB = (tA + 1) < E;
        int sA = tA + 1;
        u64 accA[4] = {0ull, 0ull, 0ull, 0ull};
        u64 accB[4] = {0ull, 0ull, 0ull, 0ull};
#pragma unroll
        for (int i4 = 0; i4 < 8; i4++) {
            float4 rr[4];
#pragma unroll
            for (int r = 0; r < 4; r++)
                rr[r] = ((const float4*)(y + (sA - 1 + r) * 36))[i4];
#pragma unroll
            for (int w = 0; w < 3; w++) {
                const float* wb = cws + w * 1024 + (i4 * 4) * 32 + o0;
                float4 va = rr[w], vb = rr[w + 1];
                u64 a0 = pack2(va.x), a1 = pack2(va.y), a2 = pack2(va.z), a3 = pack2(va.w);
                u64 b0 = pack2(vb.x), b1 = pack2(vb.y), b2 = pack2(vb.z), b3 = pack2(vb.w);
#define CSTEP(AK, BK, ROW) \
                { const ulonglong2* wk2 = (const ulonglong2*)(wb + (ROW) * 32); \
                  ulonglong2 p0 = wk2[0], p1 = wk2[1]; \
                  ffma2(accA[0], AK, p0.x); ffma2(accA[1], AK, p0.y); \
                  ffma2(accA[2], AK, p1.x); ffma2(accA[3], AK, p1.y); \
                  ffma2(accB[0], BK, p0.x); ffma2(accB[1], BK, p0.y); \
                  ffma2(accB[2], BK, p1.x); ffma2(accB[3], BK, p1.y); }
                CSTEP(a0, b0, 0)
                CSTEP(a1, b1, 1)
                CSTEP(a2, b2, 2)
                CSTEP(a3, b3, 3)
#undef CSTEP
            }
        }
        int fA = fb + tA;
        ulonglong2* co = (ulonglong2*)&gc_out[(rowbase + fA) * 32 + o0];
        co[0] = make_ulonglong2(accA[0], accA[1]);
        co[1] = make_ulonglong2(accA[2], accA[3]);
#pragma unroll
        for (int k = 0; k < 4; k++) {
            float2 f2 = unpack2(accA[k]);
            s1[2 * k] += f2.x;     s2[2 * k] += f2.x * f2.x;
            s1[2 * k + 1] += f2.y; s2[2 * k + 1] += f2.y * f2.y;
        }
        if (vB) {
            ulonglong2* cb = (ulonglong2*)&gc_out[(rowbase + fA + 1) * 32 + o0];
            cb[0] = make_ulonglong2(accB[0], accB[1]);
            cb[1] = make_ulonglong2(accB[2], accB[3]);
#pragma unroll
            for (int k = 0; k < 4; k++) {
                float2 f2 = unpack2(accB[k]);
                s1[2 * k] += f2.x;     s2[2 * k] += f2.x * f2.x;
                s1[2 * k + 1] += f2.y; s2[2 * k + 1] += f2.y * f2.y;
            }
        }
    }
#pragma unroll
    for (int off = 4; off < 32; off <<= 1) {
#pragma unroll
        for (int j = 0; j < 8; j++) {
            s1[j] += __shfl_xor_sync(0xffffffffu, s1[j], off);
            s2[j] += __shfl_xor_sync(0xffffffffu, s2[j], off);
        }
    }
    int warp = tid >> 5, lane = tid & 31;
    if (lane < 4) {
#pragma unroll
        for (int j = 0; j < 8; j++) {
            red[((warp * 4 + lane) * 8 + j) * 2 + 0] = s1[j];
            red[((warp * 4 + lane) * 8 + j) * 2 + 1] = s2[j];
        }
    }
    __syncthreads();
    if (tid < 64) {
        int kind = tid >> 5, ch = tid & 31;
        int sl = ch >> 3, j = ch & 7;
        float v = 0.f;
#pragma unroll
        for (int w2 = 0; w2 < 9; w2++) v += red[((w2 * 4 + sl) * 8 + j) * 2 + kind];
        g_part[kind * 32 + ch][pidx] = v;
    }
}

// ===== k_pre: inproj (18->32) + conv layer-0 + partials =====
__global__ __launch_bounds__(NTH, 3) void k_pre(const float* __restrict__ x,
                                                const float* __restrict__ in_w,
                                                const float* __restrict__ in_b,
                                                const float* __restrict__ cw0) {
    __shared__ __align__(16) float xs[68 * 19];    // also conv red area (needs 576)
    __shared__ __align__(16) float yb[68 * 36];
    __shared__ __align__(16) float wsin[576];
    __shared__ __align__(16) float bsin[32];
    __shared__ __align__(16) float cw[3072];
    int tid = threadIdx.x;
    int fb = blockIdx.x * T_CORE;
    int E = min(T_CORE, F_N - fb);
    size_t rowbase = (size_t)blockIdx.y * F_N;

    for (int idx = tid; idx < (E + 2) * 18; idx += NTH) {
        int s = idx / 18, i = idx - s * 18;
        int f = fb - 1 + s;
        xs[s * 19 + i] = (f >= 0 && f < F_N) ? x[(rowbase + f) * 18 + i] : 0.f;
    }
    for (int idx = tid; idx < 576; idx += NTH) wsin[idx] = in_w[idx];
    if (tid < 32) bsin[tid] = in_b[tid];
    for (int idx = tid; idx < 3072; idx += NTH) cw[idx] = cw0[idx];
    __syncthreads();

    int s = tid;
    if (s < E + 2) {
        int f = fb - 1 + s;
        u64 acc[16];
        if (f >= 0 && f < F_N) {
            const u64* b2 = (const u64*)bsin;
#pragma unroll
            for (int k = 0; k < 16; k++) acc[k] = b2[k];
#pragma unroll
            for (int i = 0; i < 18; i++) {
                u64 a2 = pack2(xs[s * 19 + i]);
                const u64* wr = (const u64*)(wsin + i * 32);
#pragma unroll
                for (int k = 0; k < 16; k++) ffma2(acc[k], a2, wr[k]);
            }
        } else {
#pragma unroll
            for (int k = 0; k < 16; k++) acc[k] = 0ull;
        }
        ulonglong2* o = (ulonglong2*)&yb[s * 36];
#pragma unroll
        for (int k = 0; k < 8; k++) o[k] = make_ulonglong2(acc[2 * k], acc[2 * k + 1]);
    }
    __syncthreads();

    for (int idx = tid; idx < E * 32; idx += NTH) {
        int t = idx >> 5, c = idx & 31;
        g_h[0][(rowbase + fb + t) * 32 + c] = yb[(t + 1) * 36 + c];
    }
    conv_phase(yb, cw, fb, E, rowbase, (int)blockIdx.y * NBX + blockIdx.x, xs, g_c[0]);
}

// ===== BN finalize: one block per channel, coalesced + vectorized =====
__global__ __launch_bounds__(256) void k_bnfin(const float* __restrict__ bng,
                                               const float* __restrict__ bnb) {
    __shared__ float rs[256], rq[256];
    int c = blockIdx.x;
    float s = 0.f, q = 0.f;
    const float4* pr = (const float4*)g_part[c];
    const float4* qr = (const float4*)g_part[32 + c];
    for (int i = threadIdx.x; i < NPART / 4; i += 256) {
        float4 a = pr[i]; s += a.x + a.y + a.z + a.w;
        float4 b = qr[i]; q += b.x + b.y + b.z + b.w;
    }
    rs[threadIdx.x] = s; rq[threadIdx.x] = q;
    __syncthreads();
    for (int off = 128; off > 0; off >>= 1) {
        if (threadIdx.x < off) {
            rs[threadIdx.x] += rs[threadIdx.x + off];
            rq[threadIdx.x] += rq[threadIdx.x + off];
        }
        __syncthreads();
    }
    if (threadIdx.x == 0) {
        float mean = rs[0] * (1.0f / BF_N);
        float var = rq[0] * (1.0f / BF_N) - mean * mean;
        float a = rsqrtf(var + 1e-5f) * bng[c];
        g_bn[0][c] = a;
        g_bn[1][c] = bnb[c] - mean * a;
    }
}

// ===== fused layer: qkv GEMM + banded attn + proj + BN/GELU + LN + next-conv / head =====
// smem floats:
//   R1 [0,2304):        ht [32][72] channel-major -> as_ [67][34] after B -> conv red
//   qs [2304,9504):     stage temp [72][33] -> [72][100] q|k|v -> y [67][36] + cw/head (at +2412)
//   wq [9504,12576)     32x96
//   wp [12576,13600)    32x32
//   params [13600,13760)
#define SMEM_APPLY (13760 * 4)
__global__ __launch_bounds__(NTH, 3) void k_apply(const float* __restrict__ qw,
                                                  const float* __restrict__ pw,
                                                  const float* __restrict__ pbias,
                                                  const float* __restrict__ lng,
                                                  const float* __restrict__ lnb,
                                                  const float* __restrict__ cwn,
                                                  const float* __restrict__ h1_w,
                                                  const float* __restrict__ h1_b,
                                                  const float* __restrict__ h2_w,
                                                  const float* __restrict__ h2_b,
                                                  float* __restrict__ out,
                                                  int src, int cidx, int last) {
    extern __shared__ float sm[];
    float* R1 = sm;               // ht then as_
    float* qs = sm + 2304;        // temp, then qkv, later y + cw/head
    float* wq = sm + 9504;
    float* wp = sm + 12576;
    float* pb = sm + 13600;
    float* lg = pb + 32;
    float* lb = lg + 32;
    float* bna = lb + 32;
    float* bnb = bna + 32;

    float* ht = R1;               // [32][72]
    float* as_ = R1;              // [67][34] (after B; ht dead); 8B-aligned rows
    float* y = qs;                // [67][36] (after C; qs rows dead)
    float* cw = qs + 2412;        // 3072 floats (conv weights OR head params)

    int tid = threadIdx.x;
    int fb = blockIdx.x * T_CORE;
    int E = min(T_CORE, F_N - fb);
    size_t rowbase = (size_t)blockIdx.y * F_N;
    const float* hsrc = g_h[src];
    float* hdst = g_h[src ^ 1];
    const float* gc_in = g_c[cidx];
    float* gc_out = g_c[cidx ^ 1];

    // ---- stage 1: coalesced LDG token-major into temp [72][33] (in qs region) ----
    float* tmp = qs;
    for (int idx = tid; idx < 72 * 32; idx += NTH) {
        int t = idx >> 5, c = idx & 31;
        int f = fb - 1 + t;
        tmp[t * 33 + c] = (f >= 0 && f < F_N) ? hsrc[(rowbase + f) * 32 + c] : 0.f;
    }
    for (int idx = tid; idx < 3072; idx += NTH) wq[idx] = qw[idx];
    for (int idx = tid; idx < 1024; idx += NTH) wp[idx] = pw[idx];
    if (tid < 32) {
        pb[tid] = pbias[tid]; lg[tid] = lng[tid]; lb[tid] = lnb[tid];
        bna[tid] = g_bn[0][tid]; bnb[tid] = g_bn[1][tid];
    }
    __syncthreads();

    // ---- stage 2: conflict-free smem transpose -> ht [32][72] channel-major ----
    for (int idx = tid; idx < 32 * 72; idx += NTH) {
        int c = idx / 72, t = idx - c * 72;
        ht[c * 72 + t] = tmp[t * 33 + c];
    }
    __syncthreads();

    // ---- Phase B: qkv GEMM (72 tok x 96 ch, K=32), 4 tok x 8 ch, FFMA2; 216 units ----
    if (tid < 216) {
        int og = tid / 18, tg = tid - og * 18;
        int t0 = tg * 4, oc = og * 8;
        u64 acc2[4][4];
#pragma unroll
        for (int a = 0; a < 4; a++)
#pragma unroll
            for (int k = 0; k < 4; k++) acc2[a][k] = 0ull;
#pragma unroll
        for (int i = 0; i < 32; i++) {
            float4 av = *reinterpret_cast<const float4*>(&ht[i * 72 + t0]);
            const ulonglong2* wr2 = reinterpret_cast<const ulonglong2*>(&wq[i * 96 + oc]);
            ulonglong2 p0 = wr2[0], p1 = wr2[1];
            u64 w0 = p0.x, w1 = p0.y, w2 = p1.x, w3 = p1.y;
            u64 a0 = pack2(av.x), a1 = pack2(av.y), a2 = pack2(av.z), a3 = pack2(av.w);
            ffma2(acc2[0][0], a0, w0); ffma2(acc2[0][1], a0, w1); ffma2(acc2[0][2], a0, w2); ffma2(acc2[0][3], a0, w3);
            ffma2(acc2[1][0], a1, w0); ffma2(acc2[1][1], a1, w1); ffma2(acc2[1][2], a1, w2); ffma2(acc2[1][3], a1, w3);
            ffma2(acc2[2][0], a2, w0); ffma2(acc2[2][1], a2, w1); ffma2(acc2[2][2], a2, w2); ffma2(acc2[2][3], a2, w3);
            ffma2(acc2[3][0], a3, w0); ffma2(acc2[3][1], a3, w1); ffma2(acc2[3][2], a3, w2); ffma2(acc2[3][3], a3, w3);
        }
#pragma unroll
        for (int a = 0; a < 4; a++) {
            ulonglong2* dst = reinterpret_cast<ulonglong2*>(&qs[(t0 + a) * 100 + oc]);
            dst[0] = make_ulonglong2(acc2[a][0], acc2[a][1]);
            dst[1] = make_ulonglong2(acc2[a][2], acc2[a][3]);
        }
    }
    __syncthreads();

    // ---- Phase C: banded attention, warp per slot (lane=channel) -> as_ (over dead ht) ----
    int warp = tid >> 5, lane = tid & 31;
    for (int rep = 0; rep < 8; rep++) {
        int s = rep * 9 + warp;
        if (s >= 67) break;
        int f = fb - 1 + s;
        if (f >= 0 && f < F_N) {
            float qv = qs[s * 100 + lane];
            float sc[3];
#pragma unroll
            for (int j = 0; j < 3; j++) {
                float p = qv * qs[(s + j) * 100 + 32 + lane];
                p += __shfl_xor_sync(0xffffffffu, p, 1);
                p += __shfl_xor_sync(0xffffffffu, p, 2);
                p += __shfl_xor_sync(0xffffffffu, p, 4);
                sc[j] = (f + j < F_N) ? p * 0.35355339059327373f : -INFINITY;
            }
            float m = fmaxf(sc[0], fmaxf(sc[1], sc[2]));
            float e0 = __expf(sc[0] - m);
            float e1 = (f + 1 < F_N) ? __expf(sc[1] - m) : 0.f;
            float e2 = (f + 2 < F_N) ? __expf(sc[2] - m) : 0.f;
            float inv = 1.f / (e0 + e1 + e2);
            float ao = (e0 * qs[s * 100 + 64 + lane]
                      + e1 * qs[(s + 1) * 100 + 64 + lane]
                      + e2 * qs[(s + 2) * 100 + 64 + lane]) * inv;
            as_[s * 34 + lane] = ao;
        } else {
            as_[s * 34 + lane] = 0.f;
        }
    }
    __syncthreads();

    // qs rows dead: overlay next-layer conv weights, or head params on the last layer
    if (!last) {
        for (int idx = tid; idx < 3072; idx += NTH) cw[idx] = cwn[idx];
    } else {
        for (int idx = tid; idx < 512; idx += NTH) cw[idx] = h1_w[idx];
        if (tid < 16) { cw[512 + tid] = h1_b[tid]; cw[528 + tid] = h2_w[tid]; }
        if (tid == 0) cw[544] = h2_b[0];
    }

    // ---- Phase D: proj + BN(c)/GELU + residual + LN + writes; TOKEN-PAIR per thread ----
    {
        int p2 = tid >> 2;
        int o0 = (tid & 3) << 3;
        int sA = p2 * 2, sB = sA + 1;
        bool vp = p2 < 34;
        int fA_ = fb - 1 + sA;
        int fB_ = fA_ + 1;
        bool fvA = vp && (fA_ >= 0) && (fA_ < F_N);
        bool fvB = vp && (sB < 67) && (fB_ >= 0) && (fB_ < F_N);
        float yvA[8], yvB[8];
#pragma unroll
        for (int j = 0; j < 8; j++) { yvA[j] = 0.f; yvB[j] = 0.f; }
        if (vp) {
            u64 accA[4], accB[4];
            const u64* pb2 = (const u64*)(pb + o0);
#pragma unroll
            for (int k = 0; k < 4; k++) { accA[k] = pb2[k]; accB[k] = pb2[k]; }
            const u64* arA = (const u64*)(as_ + sA * 34);
            const u64* arB = (const u64*)(as_ + sB * 34);
#pragma unroll
            for (int i2 = 0; i2 < 16; i2++) {
                float2 fa = unpack2(arA[i2]);
                float2 fbv = unpack2(arB[i2]);
                u64 a0 = pack2(fa.x), a1 = pack2(fa.y);
                u64 b0 = pack2(fbv.x), b1 = pack2(fbv.y);
                const ulonglong2* w02 = (const ulonglong2*)(wp + (2 * i2) * 32 + o0);
                const ulonglong2* w12 = (const ulonglong2*)(wp + (2 * i2 + 1) * 32 + o0);
                ulonglong2 pq0 = w02[0], pq1 = w02[1];
                ulonglong2 pr0 = w12[0], pr1 = w12[1];
                u64 q0 = pq0.x, q1 = pq0.y, q2 = pq1.x, q3 = pq1.y;
                u64 r0 = pr0.x, r1 = pr0.y, r2 = pr1.x, r3 = pr1.y;
                ffma2(accA[0], a0, q0); ffma2(accA[1], a0, q1); ffma2(accA[2], a0, q2); ffma2(accA[3], a0, q3);
                ffma2(accA[0], a1, r0); ffma2(accA[1], a1, r1); ffma2(accA[2], a1, r2); ffma2(accA[3], a1, r3);
                ffma2(accB[0], b0, q0); ffma2(accB[1], b0, q1); ffma2(accB[2], b0, q2); ffma2(accB[3], b0, q3);
                ffma2(accB[0], b1, r0); ffma2(accB[1], b1, r1); ffma2(accB[2], b1, r2); ffma2(accB[3], b1, r3);
            }
            if (fvA) {
                const float4* cg = (const float4*)&gc_in[(rowbase + fA_) * 32 + o0];
                float4 c0 = cg[0], c1 = cg[1];
                float cv[8] = {c0.x, c0.y, c0.z, c0.w, c1.x, c1.y, c1.z, c1.w};
#pragma unroll
                for (int k = 0; k < 4; k++) {
                    float2 pa = unpack2(accA[k]);
                    float cn0 = cv[2 * k] * bna[o0 + 2 * k] + bnb[o0 + 2 * k];
                    float cn1 = cv[2 * k + 1] * bna[o0 + 2 * k + 1] + bnb[o0 + 2 * k + 1];
                    yvA[2 * k] = gelu_f(cn0) + pa.x;
                    yvA[2 * k + 1] = gelu_f(cn1) + pa.y;
                }
            }
            if (fvB) {
                const float4* cg = (const float4*)&gc_in[(rowbase + fB_) * 32 + o0];
                float4 c0 = cg[0], c1 = cg[1];
                float cv[8] = {c0.x, c0.y, c0.z, c0.w, c1.x, c1.y, c1.z, c1.w};
#pragma unroll
                for (int k = 0; k < 4; k++) {
                    float2 pa = unpack2(accB[k]);
                    float cn0 = cv[2 * k] * bna[o0 + 2 * k] + bnb[o0 + 2 * k];
                    float cn1 = cv[2 * k + 1] * bna[o0 + 2 * k + 1] + bnb[o0 + 2 * k + 1];
                    yvB[2 * k] = gelu_f(cn0) + pa.x;
                    yvB[2 * k + 1] = gelu_f(cn1) + pa.y;
                }
            }
        }
        // LayerNorm across the 4 threads of each token (uniform shfl execution)
        float lsA = 0.f, lqA = 0.f, lsB = 0.f, lqB = 0.f;
#pragma unroll
        for (int j = 0; j < 8; j++) {
            lsA += yvA[j]; lqA += yvA[j] * yvA[j];
            lsB += yvB[j]; lqB += yvB[j] * yvB[j];
        }
        lsA += __shfl_xor_sync(0xffffffffu, lsA, 1); lsA += __shfl_xor_sync(0xffffffffu, lsA, 2);
        lqA += __shfl_xor_sync(0xffffffffu, lqA, 1); lqA += __shfl_xor_sync(0xffffffffu, lqA, 2);
        lsB += __shfl_xor_sync(0xffffffffu, lsB, 1); lsB += __shfl_xor_sync(0xffffffffu, lsB, 2);
        lqB += __shfl_xor_sync(0xffffffffu, lqB, 1); lqB += __shfl_xor_sync(0xffffffffu, lqB, 2);
        float mA = lsA * (1.f / 32.f);
        float vA = lqA * (1.f / 32.f) - mA * mA;
        float rA = rsqrtf(vA + 1e-5f);
        float mB = lsB * (1.f / 32.f);
        float vB = lqB * (1.f / 32.f) - mB * mB;
        float rB = rsqrtf(vB + 1e-5f);
        if (vp) {
            float4* yoA = (float4*)&y[sA * 36 + o0];
            if (fvA) {
                float ov[8];
#pragma unroll
                for (int j = 0; j < 8; j++)
                    ov[j] = (yvA[j] - mA) * rA * lg[o0 + j] + lb[o0 + j];
                yoA[0] = make_float4(ov[0], ov[1], ov[2], ov[3]);
                yoA[1] = make_float4(ov[4], ov[5], ov[6], ov[7]);
                if (!last && sA >= 1 && sA <= E) {
                    float4* ho = (float4*)&hdst[(rowbase + fA_) * 32 + o0];
                    ho[0] = make_float4(ov[0], ov[1], ov[2], ov[3]);
                    ho[1] = make_float4(ov[4], ov[5], ov[6], ov[7]);
                }
            } else {
                yoA[0] = make_float4(0.f, 0.f, 0.f, 0.f);
                yoA[1] = make_float4(0.f, 0.f, 0.f, 0.f);
            }
            if (sB < 67) {
                float4* yoB = (float4*)&y[sB * 36 + o0];
                if (fvB) {
                    float ov[8];
#pragma unroll
                    for (int j = 0; j < 8; j++)
                        ov[j] = (yvB[j] - mB) * rB * lg[o0 + j] + lb[o0 + j];
                    yoB[0] = make_float4(ov[0], ov[1], ov[2], ov[3]);
                    yoB[1] = make_float4(ov[4], ov[5], ov[6], ov[7]);
                    if (!last && sB >= 1 && sB <= E) {
                        float4* ho = (float4*)&hdst[(rowbase + fB_) * 32 + o0];
                        ho[0] = make_float4(ov[0], ov[1], ov[2], ov[3]);
                        ho[1] = make_float4(ov[4], ov[5], ov[6], ov[7]);
                    }
                } else {
                    yoB[0] = make_float4(0.f, 0.f, 0.f, 0.f);
                    yoB[1] = make_float4(0.f, 0.f, 0.f, 0.f);
                }
            }
        }
    }
    __syncthreads();

    if (last) {
        // ---- Phase H: head from smem y, thread per core token ----
        if (tid < E) {
            int s = tid + 1;
            int f = fb + tid;
            float hv[32];
            const float4* yr4 = (const float4*)(y + s * 36);
#pragma unroll
            for (int k = 0; k < 8; k++) {
                float4 v = yr4[k];
                hv[4 * k] = v.x; hv[4 * k + 1] = v.y; hv[4 * k + 2] = v.z; hv[4 * k + 3] = v.w;
            }
            u64 s2[8];
            const u64* wb2 = (const u64*)(cw + 512);   // h1_b
#pragma unroll
            for (int k = 0; k < 8; k++) s2[k] = wb2[k];
#pragma unroll
            for (int i = 0; i < 32; i++) {
                u64 a2 = pack2(hv[i]);
                const u64* wr = (const u64*)(cw + i * 16);
#pragma unroll
                for (int k = 0; k < 8; k++) ffma2(s2[k], a2, wr[k]);
            }
            float m = cw[544];
            const float* ws2 = cw + 528;
#pragma unroll
            for (int k = 0; k < 8; k++) {
                float2 f2 = unpack2(s2[k]);
                m += gelu_f(f2.x) * ws2[2 * k] + gelu_f(f2.y) * ws2[2 * k + 1];
            }
            out[rowbase + f] = 1.f / (1.f + expf(-m));
        }
        return;
    }

    // ---- fused next-layer conv on smem y (zero-padded rows; no tap masks) ----
    conv_phase(y, cw, fb, E, rowbase, (int)blockIdx.y * NBX + blockIdx.x, R1, gc_out);
}

// ===== launcher =====
extern "C" void kernel_launch(void* const* d_in, const int* in_sizes, int n_in,
                              void* d_out, int out_size) {
    const float* x      = (const float*)d_in[0];
    const float* in_w   = (const float*)d_in[1];
    const float* in_b   = (const float*)d_in[2];
    const float* conv_w = (const float*)d_in[3];
    const float* bn_g   = (const float*)d_in[4];
    const float* bn_b   = (const float*)d_in[5];
    const float* qkv_w  = (const float*)d_in[6];
    const float* proj_w = (const float*)d_in[7];
    const float* proj_b = (const float*)d_in[8];
    const float* ln_g   = (const float*)d_in[9];
    const float* ln_b   = (const float*)d_in[10];
    const float* h1_w   = (const float*)d_in[11];
    const float* h1_b   = (const float*)d_in[12];
    const float* h2_w   = (const float*)d_in[13];
    const float* h2_b   = (const float*)d_in[14];
    float* out = (float*)d_out;

    cudaFuncSetAttribute(k_apply, cudaFuncAttributeMaxDynamicSharedMemorySize, SMEM_APPLY);

    dim3 grid(NBX, B_N);
    k_pre<<<grid, NTH>>>(x, in_w, in_b, conv_w);
    for (int l = 0; l < 4; l++) {
        int src = l & 1;
        int cidx = l & 1;   // layer l reads g_c[l&1], writes g_c[(l&1)^1]
        int last = (l == 3) ? 1 : 0;
        k_bnfin<<<32, 256>>>(bn_g + l * 32, bn_b + l * 32);
        k_apply<<<grid, NTH, SMEM_APPLY>>>(qkv_w + l * 3072, proj_w + l * 1024,
                                           proj_b + l * 32, ln_g + l * 32, ln_b + l * 32,
                                           conv_w + (l + 1 < 4 ? l + 1 : 0) * 3072,
                                           h1_w, h1_b, h2_w, h2_b, out,
                                           src, cidx, last);
    }
}

// round 15
// speedup vs baseline: 1.0429x; 1.0429x over previous
#include <cuda_runtime.h>
#include <math.h>

#define B_N 1024
#define F_N 257
#define BF_N (B_N * F_N)
#define T_CORE 86
#define SLOTS 88            // conv/attn/y slots: f = fb-1 .. fb+86
#define NQ 92               // ht/qs token capacity (attn reads to slot+2, padded to x4)
#define NBX 3
#define NPART (NBX * B_N)   // 3072
#define NTH 288             // 9 warps

typedef unsigned long long u64;

// -------- device scratch (allocation-free) --------
__device__ __align__(16) float g_h[2][(size_t)BF_N * 32];
__device__ __align__(16) float g_c[2][(size_t)BF_N * 32];   // ping-pong per layer
__device__ __align__(16) float g_part[64][NPART];           // [kind*32+ch][block]
__device__ __align__(16) float g_bn[2][32];

__device__ __forceinline__ float gelu_f(float x) {
    return 0.5f * x * (1.0f + erff(x * 0.70710678118654752440f));
}
__device__ __forceinline__ void ffma2(u64& d, u64 a, u64 b) {
    asm("fma.rn.f32x2 %0, %1, %2, %0;" : "+l"(d) : "l"(a), "l"(b));
}
__device__ __forceinline__ u64 pack2(float x) {
    u64 r; asm("mov.b64 %0, {%1, %1};" : "=l"(r) : "f"(x)); return r;
}
__device__ __forceinline__ float2 unpack2(u64 a) {
    float2 f; asm("mov.b64 {%0, %1}, %2;" : "=f"(f.x), "=f"(f.y) : "l"(a)); return f;
}

// ===== conv (width-3 over F) on smem y [SLOTS][36] + BN partials; ALL NTH threads call =====
// Token-PAIR per thread; zero-padded y rows -> no tap masks.
__device__ __forceinline__ void conv_phase(const float* y, const float* cws,
                                           int fb, int E, size_t rowbase,
                                           int pidx, float* red, float* gc_out) {
    int tid = threadIdx.x;
    int pr = tid >> 2, o0 = (tid & 3) << 3;
    int tA = pr * 2;
    float s1[8], s2[8];
#pragma unroll
    for (int j = 0; j < 8; j++) { s1[j] = 0.f; s2[j] = 0.f; }
    if (tA < E) {
        bool vB = (tA + 1) < E;
        int sA = tA + 1;
        u64 accA[4] = {0ull, 0ull, 0ull, 0ull};
        u64 accB[4] = {0ull, 0ull, 0ull, 0ull};
#pragma unroll
        for (int i4 = 0; i4 < 8; i4++) {
            float4 rr[4];
#pragma unroll
            for (int r = 0; r < 4; r++)
                rr[r] = ((const float4*)(y + (sA - 1 + r) * 36))[i4];
#pragma unroll
            for (int w = 0; w < 3; w++) {
                const float* wb = cws + w * 1024 + (i4 * 4) * 32 + o0;
                float4 va = rr[w], vb = rr[w + 1];
                u64 a0 = pack2(va.x), a1 = pack2(va.y), a2 = pack2(va.z), a3 = pack2(va.w);
                u64 b0 = pack2(vb.x), b1 = pack2(vb.y), b2 = pack2(vb.z), b3 = pack2(vb.w);
#define CSTEP(AK, BK, ROW) \
                { const ulonglong2* wk2 = (const ulonglong2*)(wb + (ROW) * 32); \
                  ulonglong2 p0 = wk2[0], p1 = wk2[1]; \
                  ffma2(accA[0], AK, p0.x); ffma2(accA[1], AK, p0.y); \
                  ffma2(accA[2], AK, p1.x); ffma2(accA[3], AK, p1.y); \
                  ffma2(accB[0], BK, p0.x); ffma2(accB[1], BK, p0.y); \
                  ffma2(accB[2], BK, p1.x); ffma2(accB[3], BK, p1.y); }
                CSTEP(a0, b0, 0)
                CSTEP(a1, b1, 1)
                CSTEP(a2, b2, 2)
                CSTEP(a3, b3, 3)
#undef CSTEP
            }
        }
        int fA = fb + tA;
        ulonglong2* co = (ulonglong2*)&gc_out[(rowbase + fA) * 32 + o0];
        co[0] = make_ulonglong2(accA[0], accA[1]);
        co[1] = make_ulonglong2(accA[2], accA[3]);
#pragma unroll
        for (int k = 0; k < 4; k++) {
            float2 f2 = unpack2(accA[k]);
            s1[2 * k] += f2.x;     s2[2 * k] += f2.x * f2.x;
            s1[2 * k + 1] += f2.y; s2[2 * k + 1] += f2.y * f2.y;
        }
        if (vB) {
            ulonglong2* cb = (ulonglong2*)&gc_out[(rowbase + fA + 1) * 32 + o0];
            cb[0] = make_ulonglong2(accB[0], accB[1]);
            cb[1] = make_ulonglong2(accB[2], accB[3]);
#pragma unroll
            for (int k = 0; k < 4; k++) {
                float2 f2 = unpack2(accB[k]);
                s1[2 * k] += f2.x;     s2[2 * k] += f2.x * f2.x;
                s1[2 * k + 1] += f2.y; s2[2 * k + 1] += f2.y * f2.y;
            }
        }
    }
#pragma unroll
    for (int off = 4; off < 32; off <<= 1) {
#pragma unroll
        for (int j = 0; j < 8; j++) {
            s1[j] += __shfl_xor_sync(0xffffffffu, s1[j], off);
            s2[j] += __shfl_xor_sync(0xffffffffu, s2[j], off);
        }
    }
    int warp = tid >> 5, lane = tid & 31;
    if (lane < 4) {
#pragma unroll
        for (int j = 0; j < 8; j++) {
            red[((warp * 4 + lane) * 8 + j) * 2 + 0] = s1[j];
            red[((warp * 4 + lane) * 8 + j) * 2 + 1] = s2[j];
        }
    }
    __syncthreads();
    if (tid < 64) {
        int kind = tid >> 5, ch = tid & 31;
        int sl = ch >> 3, j = ch & 7;
        float v = 0.f;
#pragma unroll
        for (int w2 = 0; w2 < 9; w2++) v += red[((w2 * 4 + sl) * 8 + j) * 2 + kind];
        g_part[kind * 32 + ch][pidx] = v;
    }
}

// ===== k_pre: inproj (18->32) + conv layer-0 + partials =====
__global__ __launch_bounds__(NTH, 3) void k_pre(const float* __restrict__ x,
                                                const float* __restrict__ in_w,
                                                const float* __restrict__ in_b,
                                                const float* __restrict__ cw0) {
    __shared__ __align__(16) float xs[SLOTS * 19];   // also conv red area (needs 576)
    __shared__ __align__(16) float yb[SLOTS * 36];
    __shared__ __align__(16) float wsin[576];
    __shared__ __align__(16) float bsin[32];
    __shared__ __align__(16) float cw[3072];
    int tid = threadIdx.x;
    int fb = blockIdx.x * T_CORE;
    int E = min(T_CORE, F_N - fb);
    size_t rowbase = (size_t)blockIdx.y * F_N;

    for (int idx = tid; idx < SLOTS * 18; idx += NTH) {
        int s = idx / 18, i = idx - s * 18;
        int f = fb - 1 + s;
        xs[s * 19 + i] = (f >= 0 && f < F_N) ? x[(rowbase + f) * 18 + i] : 0.f;
    }
    for (int idx = tid; idx < 576; idx += NTH) wsin[idx] = in_w[idx];
    if (tid < 32) bsin[tid] = in_b[tid];
    for (int idx = tid; idx < 3072; idx += NTH) cw[idx] = cw0[idx];
    __syncthreads();

    int s = tid;
    if (s < SLOTS) {
        int f = fb - 1 + s;
        u64 acc[16];
        if (f >= 0 && f < F_N) {
            const u64* b2 = (const u64*)bsin;
#pragma unroll
            for (int k = 0; k < 16; k++) acc[k] = b2[k];
#pragma unroll
            for (int i = 0; i < 18; i++) {
                u64 a2 = pack2(xs[s * 19 + i]);
                const u64* wr = (const u64*)(wsin + i * 32);
#pragma unroll
                for (int k = 0; k < 16; k++) ffma2(acc[k], a2, wr[k]);
            }
        } else {
#pragma unroll
            for (int k = 0; k < 16; k++) acc[k] = 0ull;
        }
        ulonglong2* o = (ulonglong2*)&yb[s * 36];
#pragma unroll
        for (int k = 0; k < 8; k++) o[k] = make_ulonglong2(acc[2 * k], acc[2 * k + 1]);
    }
    __syncthreads();

    for (int idx = tid; idx < E * 32; idx += NTH) {
        int t = idx >> 5, c = idx & 31;
        g_h[0][(rowbase + fb + t) * 32 + c] = yb[(t + 1) * 36 + c];
    }
    conv_phase(yb, cw, fb, E, rowbase, (int)blockIdx.y * NBX + blockIdx.x, xs, g_c[0]);
}

// ===== BN finalize: one block per channel, coalesced + vectorized =====
__global__ __launch_bounds__(256) void k_bnfin(const float* __restrict__ bng,
                                               const float* __restrict__ bnb) {
    __shared__ float rs[256], rq[256];
    int c = blockIdx.x;
    float s = 0.f, q = 0.f;
    const float4* pr = (const float4*)g_part[c];
    const float4* qr = (const float4*)g_part[32 + c];
    for (int i = threadIdx.x; i < NPART / 4; i += 256) {
        float4 a = pr[i]; s += a.x + a.y + a.z + a.w;
        float4 b = qr[i]; q += b.x + b.y + b.z + b.w;
    }
    rs[threadIdx.x] = s; rq[threadIdx.x] = q;
    __syncthreads();
    for (int off = 128; off > 0; off >>= 1) {
        if (threadIdx.x < off) {
            rs[threadIdx.x] += rs[threadIdx.x + off];
            rq[threadIdx.x] += rq[threadIdx.x + off];
        }
        __syncthreads();
    }
    if (threadIdx.x == 0) {
        float mean = rs[0] * (1.0f / BF_N);
        float var = rq[0] * (1.0f / BF_N) - mean * mean;
        float a = rsqrtf(var + 1e-5f) * bng[c];
        g_bn[0][c] = a;
        g_bn[1][c] = bnb[c] - mean * a;
    }
}

// ===== fused layer: qkv GEMM + banded attn + proj + BN/GELU + LN + next-conv / head =====
// smem floats:
//   R1 [0,2992):        ht [32][92] -> as_ [88][34] after B -> conv red
//   qs [2992,12192):    stage temp [92][33] -> [92][100] q|k|v -> y [88][36] + cw/head (at +3168)
//   wq [12192,15264)    32x96
//   wp [15264,16288)    32x32
//   params [16288,16448)
#define SMEM_APPLY (16448 * 4)
__global__ __launch_bounds__(NTH, 3) void k_apply(const float* __restrict__ qw,
                                                  const float* __restrict__ pw,
                                                  const float* __restrict__ pbias,
                                                  const float* __restrict__ lng,
                                                  const float* __restrict__ lnb,
                                                  const float* __restrict__ cwn,
                                                  const float* __restrict__ h1_w,
                                                  const float* __restrict__ h1_b,
                                                  const float* __restrict__ h2_w,
                                                  const float* __restrict__ h2_b,
                                                  float* __restrict__ out,
                                                  int src, int cidx, int last) {
    extern __shared__ float sm[];
    float* R1 = sm;               // ht then as_
    float* qs = sm + 2992;        // temp, then qkv, later y + cw/head
    float* wq = sm + 12192;
    float* wp = sm + 15264;
    float* pb = sm + 16288;
    float* lg = pb + 32;
    float* lb = lg + 32;
    float* bna = lb + 32;
    float* bnb = bna + 32;

    float* ht = R1;               // [32][92]
    float* as_ = R1;              // [88][34] (after B; ht dead); 8B-aligned rows
    float* y = qs;                // [88][36] (after C; qs rows dead)
    float* cw = qs + 3168;        // 3072 floats (conv weights OR head params)

    int tid = threadIdx.x;
    int fb = blockIdx.x * T_CORE;
    int E = min(T_CORE, F_N - fb);
    size_t rowbase = (size_t)blockIdx.y * F_N;
    const float* hsrc = g_h[src];
    float* hdst = g_h[src ^ 1];
    const float* gc_in = g_c[cidx];
    float* gc_out = g_c[cidx ^ 1];

    // ---- stage 1: coalesced LDG token-major into temp [92][33] (in qs region) ----
    float* tmp = qs;
    for (int idx = tid; idx < NQ * 32; idx += NTH) {
        int t = idx >> 5, c = idx & 31;
        int f = fb - 1 + t;
        tmp[t * 33 + c] = (f >= 0 && f < F_N) ? hsrc[(rowbase + f) * 32 + c] : 0.f;
    }
    for (int idx = tid; idx < 3072; idx += NTH) wq[idx] = qw[idx];
    for (int idx = tid; idx < 1024; idx += NTH) wp[idx] = pw[idx];
    if (tid < 32) {
        pb[tid] = pbias[tid]; lg[tid] = lng[tid]; lb[tid] = lnb[tid];
        bna[tid] = g_bn[0][tid]; bnb[tid] = g_bn[1][tid];
    }
    __syncthreads();

    // ---- stage 2: conflict-free smem transpose -> ht [32][92] channel-major ----
    for (int idx = tid; idx < 32 * NQ; idx += NTH) {
        int c = idx / NQ, t = idx - c * NQ;
        ht[c * NQ + t] = tmp[t * 33 + c];
    }
    __syncthreads();

    // ---- Phase B: qkv GEMM (92 tok x 96 ch, K=32), 4 tok x 8 ch, FFMA2; 276 units ----
    if (tid < 276) {
        int og = tid / 23, tg = tid - og * 23;
        int t0 = tg * 4, oc = og * 8;
        u64 acc2[4][4];
#pragma unroll
        for (int a = 0; a < 4; a++)
#pragma unroll
            for (int k = 0; k < 4; k++) acc2[a][k] = 0ull;
#pragma unroll
        for (int i = 0; i < 32; i++) {
            float4 av = *reinterpret_cast<const float4*>(&ht[i * NQ + t0]);
            const ulonglong2* wr2 = reinterpret_cast<const ulonglong2*>(&wq[i * 96 + oc]);
            ulonglong2 p0 = wr2[0], p1 = wr2[1];
            u64 w0 = p0.x, w1 = p0.y, w2 = p1.x, w3 = p1.y;
            u64 a0 = pack2(av.x), a1 = pack2(av.y), a2 = pack2(av.z), a3 = pack2(av.w);
            ffma2(acc2[0][0], a0, w0); ffma2(acc2[0][1], a0, w1); ffma2(acc2[0][2], a0, w2); ffma2(acc2[0][3], a0, w3);
            ffma2(acc2[1][0], a1, w0); ffma2(acc2[1][1], a1, w1); ffma2(acc2[1][2], a1, w2); ffma2(acc2[1][3], a1, w3);
            ffma2(acc2[2][0], a2, w0); ffma2(acc2[2][1], a2, w1); ffma2(acc2[2][2], a2, w2); ffma2(acc2[2][3], a2, w3);
            ffma2(acc2[3][0], a3, w0); ffma2(acc2[3][1], a3, w1); ffma2(acc2[3][2], a3, w2); ffma2(acc2[3][3], a3, w3);
        }
#pragma unroll
        for (int a = 0; a < 4; a++) {
            ulonglong2* dst = reinterpret_cast<ulonglong2*>(&qs[(t0 + a) * 100 + oc]);
            dst[0] = make_ulonglong2(acc2[a][0], acc2[a][1]);
            dst[1] = make_ulonglong2(acc2[a][2], acc2[a][3]);
        }
    }
    __syncthreads();

    // ---- Phase C: banded attention, warp per slot (lane=channel) -> as_; no break (ILP) ----
    int warp = tid >> 5, lane = tid & 31;
#pragma unroll
    for (int rep = 0; rep < 10; rep++) {
        int s = rep * 9 + warp;
        if (s < SLOTS) {
            int f = fb - 1 + s;
            if (f >= 0 && f < F_N) {
                float qv = qs[s * 100 + lane];
                float sc[3];
#pragma unroll
                for (int j = 0; j < 3; j++) {
                    float p = qv * qs[(s + j) * 100 + 32 + lane];
                    p += __shfl_xor_sync(0xffffffffu, p, 1);
                    p += __shfl_xor_sync(0xffffffffu, p, 2);
                    p += __shfl_xor_sync(0xffffffffu, p, 4);
                    sc[j] = (f + j < F_N) ? p * 0.35355339059327373f : -INFINITY;
                }
                float m = fmaxf(sc[0], fmaxf(sc[1], sc[2]));
                float e0 = __expf(sc[0] - m);
                float e1 = (f + 1 < F_N) ? __expf(sc[1] - m) : 0.f;
                float e2 = (f + 2 < F_N) ? __expf(sc[2] - m) : 0.f;
                float inv = 1.f / (e0 + e1 + e2);
                float ao = (e0 * qs[s * 100 + 64 + lane]
                          + e1 * qs[(s + 1) * 100 + 64 + lane]
                          + e2 * qs[(s + 2) * 100 + 64 + lane]) * inv;
                as_[s * 34 + lane] = ao;
            } else {
                as_[s * 34 + lane] = 0.f;
            }
        }
    }
    __syncthreads();

    // qs rows dead: overlay next-layer conv weights, or head params on the last layer
    if (!last) {
        for (int idx = tid; idx < 3072; idx += NTH) cw[idx] = cwn[idx];
    } else {
        for (int idx = tid; idx < 512; idx += NTH) cw[idx] = h1_w[idx];
        if (tid < 16) { cw[512 + tid] = h1_b[tid]; cw[528 + tid] = h2_w[tid]; }
        if (tid == 0) cw[544] = h2_b[0];
    }

    // ---- Phase D: proj + BN(c)/GELU + residual + LN + writes; TOKEN-PAIR per thread ----
    {
        int p2 = tid >> 2;
        int o0 = (tid & 3) << 3;
        int sA = p2 * 2, sB = sA + 1;
        bool vp = p2 < 44;
        int fA_ = fb - 1 + sA;
        int fB_ = fA_ + 1;
        bool fvA = vp && (fA_ >= 0) && (fA_ < F_N);
        bool fvB = vp && (fB_ >= 0) && (fB_ < F_N);
        float yvA[8], yvB[8];
#pragma unroll
        for (int j = 0; j < 8; j++) { yvA[j] = 0.f; yvB[j] = 0.f; }
        if (vp) {
            u64 accA[4], accB[4];
            const u64* pb2 = (const u64*)(pb + o0);
#pragma unroll
            for (int k = 0; k < 4; k++) { accA[k] = pb2[k]; accB[k] = pb2[k]; }
            const u64* arA = (const u64*)(as_ + sA * 34);
            const u64* arB = (const u64*)(as_ + sB * 34);
#pragma unroll
            for (int i2 = 0; i2 < 16; i2++) {
                float2 fa = unpack2(arA[i2]);
                float2 fbv = unpack2(arB[i2]);
                u64 a0 = pack2(fa.x), a1 = pack2(fa.y);
                u64 b0 = pack2(fbv.x), b1 = pack2(fbv.y);
                const ulonglong2* w02 = (const ulonglong2*)(wp + (2 * i2) * 32 + o0);
                const ulonglong2* w12 = (const ulonglong2*)(wp + (2 * i2 + 1) * 32 + o0);
                ulonglong2 pq0 = w02[0], pq1 = w02[1];
                ulonglong2 pr0 = w12[0], pr1 = w12[1];
                u64 q0 = pq0.x, q1 = pq0.y, q2 = pq1.x, q3 = pq1.y;
                u64 r0 = pr0.x, r1 = pr0.y, r2 = pr1.x, r3 = pr1.y;
                ffma2(accA[0], a0, q0); ffma2(accA[1], a0, q1); ffma2(accA[2], a0, q2); ffma2(accA[3], a0, q3);
                ffma2(accA[0], a1, r0); ffma2(accA[1], a1, r1); ffma2(accA[2], a1, r2); ffma2(accA[3], a1, r3);
                ffma2(accB[0], b0, q0); ffma2(accB[1], b0, q1); ffma2(accB[2], b0, q2); ffma2(accB[3], b0, q3);
                ffma2(accB[0], b1, r0); ffma2(accB[1], b1, r1); ffma2(accB[2], b1, r2); ffma2(accB[3], b1, r3);
            }
            if (fvA) {
                const float4* cg = (const float4*)&gc_in[(rowbase + fA_) * 32 + o0];
                float4 c0 = cg[0], c1 = cg[1];
                float cv[8] = {c0.x, c0.y, c0.z, c0.w, c1.x, c1.y, c1.z, c1.w};
#pragma unroll
                for (int k = 0; k < 4; k++) {
                    float2 pa = unpack2(accA[k]);
                    float cn0 = cv[2 * k] * bna[o0 + 2 * k] + bnb[o0 + 2 * k];
                    float cn1 = cv[2 * k + 1] * bna[o0 + 2 * k + 1] + bnb[o0 + 2 * k + 1];
                    yvA[2 * k] = gelu_f(cn0) + pa.x;
                    yvA[2 * k + 1] = gelu_f(cn1) + pa.y;
                }
            }
            if (fvB) {
                const float4* cg = (const float4*)&gc_in[(rowbase + fB_) * 32 + o0];
                float4 c0 = cg[0], c1 = cg[1];
                float cv[8] = {c0.x, c0.y, c0.z, c0.w, c1.x, c1.y, c1.z, c1.w};
#pragma unroll
                for (int k = 0; k < 4; k++) {
                    float2 pa = unpack2(accB[k]);
                    float cn0 = cv[2 * k] * bna[o0 + 2 * k] + bnb[o0 + 2 * k];
                    float cn1 = cv[2 * k + 1] * bna[o0 + 2 * k + 1] + bnb[o0 + 2 * k + 1];
                    yvB[2 * k] = gelu_f(cn0) + pa.x;
                    yvB[2 * k + 1] = gelu_f(cn1) + pa.y;
                }
            }
        }
        // LayerNorm across the 4 threads of each token (uniform shfl execution)
        float lsA = 0.f, lqA = 0.f, lsB = 0.f, lqB = 0.f;
#pragma unroll
        for (int j = 0; j < 8; j++) {
            lsA += yvA[j]; lqA += yvA[j] * yvA[j];
            lsB += yvB[j]; lqB += yvB[j] * yvB[j];
        }
        lsA += __shfl_xor_sync(0xffffffffu, lsA, 1); lsA += __shfl_xor_sync(0xffffffffu, lsA, 2);
        lqA += __shfl_xor_sync(0xffffffffu, lqA, 1); lqA += __shfl_xor_sync(0xffffffffu, lqA, 2);
        lsB += __shfl_xor_sync(0xffffffffu, lsB, 1); lsB += __shfl_xor_sync(0xffffffffu, lsB, 2);
        lqB += __shfl_xor_sync(0xffffffffu, lqB, 1); lqB += __shfl_xor_sync(0xffffffffu, lqB, 2);
        float mA = lsA * (1.f / 32.f);
        float vA = lqA * (1.f / 32.f) - mA * mA;
        float rA = rsqrtf(vA + 1e-5f);
        float mB = lsB * (1.f / 32.f);
        float vB2 = lqB * (1.f / 32.f) - mB * mB;
        float rB = rsqrtf(vB2 + 1e-5f);
        if (vp) {
            float4* yoA = (float4*)&y[sA * 36 + o0];
            if (fvA) {
                float ov[8];
#pragma unroll
                for (int j = 0; j < 8; j++)
                    ov[j] = (yvA[j] - mA) * rA * lg[o0 + j] + lb[o0 + j];
                yoA[0] = make_float4(ov[0], ov[1], ov[2], ov[3]);
                yoA[1] = make_float4(ov[4], ov[5], ov[6], ov[7]);
                if (!last && sA >= 1 && sA <= E) {
                    float4* ho = (float4*)&hdst[(rowbase + fA_) * 32 + o0];
                    ho[0] = make_float4(ov[0], ov[1], ov[2], ov[3]);
                    ho[1] = make_float4(ov[4], ov[5], ov[6], ov[7]);
                }
            } else {
                yoA[0] = make_float4(0.f, 0.f, 0.f, 0.f);
                yoA[1] = make_float4(0.f, 0.f, 0.f, 0.f);
            }
            float4* yoB = (float4*)&y[sB * 36 + o0];
            if (fvB) {
                float ov[8];
#pragma unroll
                for (int j = 0; j < 8; j++)
                    ov[j] = (yvB[j] - mB) * rB * lg[o0 + j] + lb[o0 + j];
                yoB[0] = make_float4(ov[0], ov[1], ov[2], ov[3]);
                yoB[1] = make_float4(ov[4], ov[5], ov[6], ov[7]);
                if (!last && sB >= 1 && sB <= E) {
                    float4* ho = (float4*)&hdst[(rowbase + fB_) * 32 + o0];
                    ho[0] = make_float4(ov[0], ov[1], ov[2], ov[3]);
                    ho[1] = make_float4(ov[4], ov[5], ov[6], ov[7]);
                }
            } else {
                yoB[0] = make_float4(0.f, 0.f, 0.f, 0.f);
                yoB[1] = make_float4(0.f, 0.f, 0.f, 0.f);
            }
        }
    }
    __syncthreads();

    if (last) {
        // ---- Phase H: head from smem y, thread per core token ----
        if (tid < E) {
            int s = tid + 1;
            int f = fb + tid;
            float hv[32];
            const float4* yr4 = (const float4*)(y + s * 36);
#pragma unroll
            for (int k = 0; k < 8; k++) {
                float4 v = yr4[k];
                hv[4 * k] = v.x; hv[4 * k + 1] = v.y; hv[4 * k + 2] = v.z; hv[4 * k + 3] = v.w;
            }
            u64 s2[8];
            const u64* wb2 = (const u64*)(cw + 512);   // h1_b
#pragma unroll
            for (int k = 0; k < 8; k++) s2[k] = wb2[k];
#pragma unroll
            for (int i = 0; i < 32; i++) {
                u64 a2 = pack2(hv[i]);
                const u64* wr = (const u64*)(cw + i * 16);
#pragma unroll
                for (int k = 0; k < 8; k++) ffma2(s2[k], a2, wr[k]);
            }
            float m = cw[544];
            const float* ws2 = cw + 528;
#pragma unroll
            for (int k = 0; k < 8; k++) {
                float2 f2 = unpack2(s2[k]);
                m += gelu_f(f2.x) * ws2[2 * k] + gelu_f(f2.y) * ws2[2 * k + 1];
            }
            out[rowbase + f] = 1.f / (1.f + expf(-m));
        }
        return;
    }

    // ---- fused next-layer conv on smem y (zero-padded rows; no tap masks) ----
    conv_phase(y, cw, fb, E, rowbase, (int)blockIdx.y * NBX + blockIdx.x, R1, gc_out);
}

// ===== launcher =====
extern "C" void kernel_launch(void* const* d_in, const int* in_sizes, int n_in,
                              void* d_out, int out_size) {
    const float* x      = (const float*)d_in[0];
    const float* in_w   = (const float*)d_in[1];
    const float* in_b   = (const float*)d_in[2];
    const float* conv_w = (const float*)d_in[3];
    const float* bn_g   = (const float*)d_in[4];
    const float* bn_b   = (const float*)d_in[5];
    const float* qkv_w  = (const float*)d_in[6];
    const float* proj_w = (const float*)d_in[7];
    const float* proj_b = (const float*)d_in[8];
    const float* ln_g   = (const float*)d_in[9];
    const float* ln_b   = (const float*)d_in[10];
    const float* h1_w   = (const float*)d_in[11];
    const float* h1_b   = (const float*)d_in[12];
    const float* h2_w   = (const float*)d_in[13];
    const float* h2_b   = (const float*)d_in[14];
    float* out = (float*)d_out;

    cudaFuncSetAttribute(k_apply, cudaFuncAttributeMaxDynamicSharedMemorySize, SMEM_APPLY);

    dim3 grid(NBX, B_N);
    k_pre<<<grid, NTH>>>(x, in_w, in_b, conv_w);
    for (int l = 0; l < 4; l++) {
        int src = l & 1;
        int cidx = l & 1;   // layer l reads g_c[l&1], writes g_c[(l&1)^1]
        int last = (l == 3) ? 1 : 0;
        k_bnfin<<<32, 256>>>(bn_g + l * 32, bn_b + l * 32);
        k_apply<<<grid, NTH, SMEM_APPLY>>>(qkv_w + l * 3072, proj_w + l * 1024,
                                           proj_b + l * 32, ln_g + l * 32, ln_b + l * 32,
                                           conv_w + (l + 1 < 4 ? l + 1 : 0) * 3072,
                                           h1_w, h1_b, h2_w, h2_b, out,
                                           src, cidx, last);
    }
}

// round 16
// speedup vs baseline: 1.0646x; 1.0208x over previous
#include <cuda_runtime.h>
#include <math.h>

#define B_N 1024
#define F_N 257
#define BF_N (B_N * F_N)
#define T_CORE 86
#define SLOTS 88            // conv/attn/y slots: f = fb-1 .. fb+86
#define NQ 92               // ht/qs token capacity
#define NBX 3
#define NPART (NBX * B_N)   // 3072
#define NTH 288             // 9 warps

typedef unsigned long long u64;

// -------- device scratch (allocation-free) --------
__device__ __align__(16) float g_h[2][(size_t)BF_N * 32];
__device__ __align__(16) float g_c[2][(size_t)BF_N * 32];   // ping-pong per layer
__device__ __align__(16) float g_part[64][NPART];           // [kind*32+ch][block]
__device__ __align__(16) float g_bn[2][32];

__device__ __forceinline__ float gelu_f(float x) {
    return 0.5f * x * (1.0f + erff(x * 0.70710678118654752440f));
}
__device__ __forceinline__ void ffma2(u64& d, u64 a, u64 b) {
    asm("fma.rn.f32x2 %0, %1, %2, %0;" : "+l"(d) : "l"(a), "l"(b));
}
__device__ __forceinline__ u64 pack2(float x) {
    u64 r; asm("mov.b64 %0, {%1, %1};" : "=l"(r) : "f"(x)); return r;
}
__device__ __forceinline__ float2 unpack2(u64 a) {
    float2 f; asm("mov.b64 {%0, %1}, %2;" : "=f"(f.x), "=f"(f.y) : "l"(a)); return f;
}

// ===== conv (width-3 over F) on smem y [SLOTS][36] + BN partials; ALL NTH threads call =====
__device__ __forceinline__ void conv_phase(const float* y, const float* cws,
                                           int fb, int E, size_t rowbase,
                                           int pidx, float* red, float* gc_out) {
    int tid = threadIdx.x;
    int pr = tid >> 2, o0 = (tid & 3) << 3;
    int tA = pr * 2;
    float s1[8], s2[8];
#pragma unroll
    for (int j = 0; j < 8; j++) { s1[j] = 0.f; s2[j] = 0.f; }
    if (tA < E) {
        bool vB = (tA + 1) < E;
        int sA = tA + 1;
        u64 accA[4] = {0ull, 0ull, 0ull, 0ull};
        u64 accB[4] = {0ull, 0ull, 0ull, 0ull};
#pragma unroll
        for (int i4 = 0; i4 < 8; i4++) {
            float4 rr[4];
#pragma unroll
            for (int r = 0; r < 4; r++)
                rr[r] = ((const float4*)(y + (sA - 1 + r) * 36))[i4];
#pragma unroll
            for (int w = 0; w < 3; w++) {
                const float* wb = cws + w * 1024 + (i4 * 4) * 32 + o0;
                float4 va = rr[w], vb = rr[w + 1];
                u64 a0 = pack2(va.x), a1 = pack2(va.y), a2 = pack2(va.z), a3 = pack2(va.w);
                u64 b0 = pack2(vb.x), b1 = pack2(vb.y), b2 = pack2(vb.z), b3 = pack2(vb.w);
#define CSTEP(AK, BK, ROW) \
                { const ulonglong2* wk2 = (const ulonglong2*)(wb + (ROW) * 32); \
                  ulonglong2 p0 = wk2[0], p1 = wk2[1]; \
                  ffma2(accA[0], AK, p0.x); ffma2(accA[1], AK, p0.y); \
                  ffma2(accA[2], AK, p1.x); ffma2(accA[3], AK, p1.y); \
                  ffma2(accB[0], BK, p0.x); ffma2(accB[1], BK, p0.y); \
                  ffma2(accB[2], BK, p1.x); ffma2(accB[3], BK, p1.y); }
                CSTEP(a0, b0, 0)
                CSTEP(a1, b1, 1)
                CSTEP(a2, b2, 2)
                CSTEP(a3, b3, 3)
#undef CSTEP
            }
        }
        int fA = fb + tA;
        ulonglong2* co = (ulonglong2*)&gc_out[(rowbase + fA) * 32 + o0];
        co[0] = make_ulonglong2(accA[0], accA[1]);
        co[1] = make_ulonglong2(accA[2], accA[3]);
#pragma unroll
        for (int k = 0; k < 4; k++) {
            float2 f2 = unpack2(accA[k]);
            s1[2 * k] += f2.x;     s2[2 * k] += f2.x * f2.x;
            s1[2 * k + 1] += f2.y; s2[2 * k + 1] += f2.y * f2.y;
        }
        if (vB) {
            ulonglong2* cb = (ulonglong2*)&gc_out[(rowbase + fA + 1) * 32 + o0];
            cb[0] = make_ulonglong2(accB[0], accB[1]);
            cb[1] = make_ulonglong2(accB[2], accB[3]);
#pragma unroll
            for (int k = 0; k < 4; k++) {
                float2 f2 = unpack2(accB[k]);
                s1[2 * k] += f2.x;     s2[2 * k] += f2.x * f2.x;
                s1[2 * k + 1] += f2.y; s2[2 * k + 1] += f2.y * f2.y;
            }
        }
    }
#pragma unroll
    for (int off = 4; off < 32; off <<= 1) {
#pragma unroll
        for (int j = 0; j < 8; j++) {
            s1[j] += __shfl_xor_sync(0xffffffffu, s1[j], off);
            s2[j] += __shfl_xor_sync(0xffffffffu, s2[j], off);
        }
    }
    int warp = tid >> 5, lane = tid & 31;
    if (lane < 4) {
#pragma unroll
        for (int j = 0; j < 8; j++) {
            red[((warp * 4 + lane) * 8 + j) * 2 + 0] = s1[j];
            red[((warp * 4 + lane) * 8 + j) * 2 + 1] = s2[j];
        }
    }
    __syncthreads();
    if (tid < 64) {
        int kind = tid >> 5, ch = tid & 31;
        int sl = ch >> 3, j = ch & 7;
        float v = 0.f;
#pragma unroll
        for (int w2 = 0; w2 < 9; w2++) v += red[((w2 * 4 + sl) * 8 + j) * 2 + kind];
        g_part[kind * 32 + ch][pidx] = v;
    }
}

// ===== k_pre: inproj (18->32, 2 threads/token) + conv layer-0 + partials =====
__global__ __launch_bounds__(NTH, 3) void k_pre(const float* __restrict__ x,
                                                const float* __restrict__ in_w,
                                                const float* __restrict__ in_b,
                                                const float* __restrict__ cw0) {
    __shared__ __align__(16) float xs[SLOTS * 19];   // also conv red area (needs 576)
    __shared__ __align__(16) float yb[SLOTS * 36];
    __shared__ __align__(16) float wsin[576];
    __shared__ __align__(16) float bsin[32];
    __shared__ __align__(16) float cw[3072];
    int tid = threadIdx.x;
    int fb = blockIdx.x * T_CORE;
    int E = min(T_CORE, F_N - fb);
    size_t rowbase = (size_t)blockIdx.y * F_N;

    for (int idx = tid; idx < SLOTS * 18; idx += NTH) {
        int s = idx / 18, i = idx - s * 18;
        int f = fb - 1 + s;
        xs[s * 19 + i] = (f >= 0 && f < F_N) ? x[(rowbase + f) * 18 + i] : 0.f;
    }
    for (int idx = tid; idx < 576; idx += NTH) wsin[idx] = in_w[idx];
    if (tid < 32) bsin[tid] = in_b[tid];
    for (int idx = tid; idx < 3072; idx += NTH) cw[idx] = cw0[idx];
    __syncthreads();

    {
        int s = tid >> 1, half = tid & 1;
        if (s < SLOTS) {
            int f = fb - 1 + s;
            int c0 = half * 16;
            u64 acc[8];
            if (f >= 0 && f < F_N) {
                const u64* b2 = (const u64*)(bsin + c0);
#pragma unroll
                for (int k = 0; k < 8; k++) acc[k] = b2[k];
#pragma unroll
                for (int i = 0; i < 18; i++) {
                    u64 a2 = pack2(xs[s * 19 + i]);
                    const u64* wr = (const u64*)(wsin + i * 32 + c0);
#pragma unroll
                    for (int k = 0; k < 8; k++) ffma2(acc[k], a2, wr[k]);
                }
            } else {
#pragma unroll
                for (int k = 0; k < 8; k++) acc[k] = 0ull;
            }
            ulonglong2* o = (ulonglong2*)&yb[s * 36 + c0];
#pragma unroll
            for (int k = 0; k < 4; k++) o[k] = make_ulonglong2(acc[2 * k], acc[2 * k + 1]);
        }
    }
    __syncthreads();

    for (int idx = tid; idx < E * 32; idx += NTH) {
        int t = idx >> 5, c = idx & 31;
        g_h[0][(rowbase + fb + t) * 32 + c] = yb[(t + 1) * 36 + c];
    }
    conv_phase(yb, cw, fb, E, rowbase, (int)blockIdx.y * NBX + blockIdx.x, xs, g_c[0]);
}

// ===== BN finalize =====
__global__ __launch_bounds__(256) void k_bnfin(const float* __restrict__ bng,
                                               const float* __restrict__ bnb) {
    __shared__ float rs[256], rq[256];
    int c = blockIdx.x;
    float s = 0.f, q = 0.f;
    const float4* pr = (const float4*)g_part[c];
    const float4* qr = (const float4*)g_part[32 + c];
    for (int i = threadIdx.x; i < NPART / 4; i += 256) {
        float4 a = pr[i]; s += a.x + a.y + a.z + a.w;
        float4 b = qr[i]; q += b.x + b.y + b.z + b.w;
    }
    rs[threadIdx.x] = s; rq[threadIdx.x] = q;
    __syncthreads();
    for (int off = 128; off > 0; off >>= 1) {
        if (threadIdx.x < off) {
            rs[threadIdx.x] += rs[threadIdx.x + off];
            rq[threadIdx.x] += rq[threadIdx.x + off];
        }
        __syncthreads();
    }
    if (threadIdx.x == 0) {
        float mean = rs[0] * (1.0f / BF_N);
        float var = rq[0] * (1.0f / BF_N) - mean * mean;
        float a = rsqrtf(var + 1e-5f) * bng[c];
        g_bn[0][c] = a;
        g_bn[1][c] = bnb[c] - mean * a;
    }
}

// ===== fused layer =====
#define SMEM_APPLY (16448 * 4)
__global__ __launch_bounds__(NTH, 3) void k_apply(const float* __restrict__ qw,
                                                  const float* __restrict__ pw,
                                                  const float* __restrict__ pbias,
                                                  const float* __restrict__ lng,
                                                  const float* __restrict__ lnb,
                                                  const float* __restrict__ cwn,
                                                  const float* __restrict__ h1_w,
                                                  const float* __restrict__ h1_b,
                                                  const float* __restrict__ h2_w,
                                                  const float* __restrict__ h2_b,
                                                  float* __restrict__ out,
                                                  int src, int cidx, int last) {
    extern __shared__ float sm[];
    float* R1 = sm;               // ht then as_
    float* qs = sm + 2992;        // temp, then qkv, later y + cw/head
    float* wq = sm + 12192;
    float* wp = sm + 15264;
    float* pb = sm + 16288;
    float* lg = pb + 32;
    float* lb = lg + 32;
    float* bna = lb + 32;
    float* bnb = bna + 32;

    float* ht = R1;               // [32][92]
    float* as_ = R1;              // [88][34]
    float* y = qs;                // [88][36]
    float* cw = qs + 3168;        // 3072 floats (conv weights OR head params)

    int tid = threadIdx.x;
    int fb = blockIdx.x * T_CORE;
    int E = min(T_CORE, F_N - fb);
    size_t rowbase = (size_t)blockIdx.y * F_N;
    const float* hsrc = g_h[src];
    float* hdst = g_h[src ^ 1];
    const float* gc_in = g_c[cidx];
    float* gc_out = g_c[cidx ^ 1];

    // ---- stage 1: coalesced LDG token-major into temp [92][33] ----
    float* tmp = qs;
    for (int idx = tid; idx < NQ * 32; idx += NTH) {
        int t = idx >> 5, c = idx & 31;
        int f = fb - 1 + t;
        tmp[t * 33 + c] = (f >= 0 && f < F_N) ? hsrc[(rowbase + f) * 32 + c] : 0.f;
    }
    for (int idx = tid; idx < 3072; idx += NTH) wq[idx] = qw[idx];
    for (int idx = tid; idx < 1024; idx += NTH) wp[idx] = pw[idx];
    if (tid < 32) {
        pb[tid] = pbias[tid]; lg[tid] = lng[tid]; lb[tid] = lnb[tid];
        bna[tid] = g_bn[0][tid]; bnb[tid] = g_bn[1][tid];
    }
    __syncthreads();

    // ---- stage 2: conflict-free smem transpose -> ht [32][92] ----
    for (int idx = tid; idx < 32 * NQ; idx += NTH) {
        int c = idx / NQ, t = idx - c * NQ;
        ht[c * NQ + t] = tmp[t * 33 + c];
    }
    __syncthreads();

    // ---- Phase B: qkv GEMM (92 tok x 96 ch, K=32), 4 tok x 8 ch, FFMA2; 276 units ----
    if (tid < 276) {
        int og = tid / 23, tg = tid - og * 23;
        int t0 = tg * 4, oc = og * 8;
        u64 acc2[4][4];
#pragma unroll
        for (int a = 0; a < 4; a++)
#pragma unroll
            for (int k = 0; k < 4; k++) acc2[a][k] = 0ull;
#pragma unroll
        for (int i = 0; i < 32; i++) {
            float4 av = *reinterpret_cast<const float4*>(&ht[i * NQ + t0]);
            const ulonglong2* wr2 = reinterpret_cast<const ulonglong2*>(&wq[i * 96 + oc]);
            ulonglong2 p0 = wr2[0], p1 = wr2[1];
            u64 w0 = p0.x, w1 = p0.y, w2 = p1.x, w3 = p1.y;
            u64 a0 = pack2(av.x), a1 = pack2(av.y), a2 = pack2(av.z), a3 = pack2(av.w);
            ffma2(acc2[0][0], a0, w0); ffma2(acc2[0][1], a0, w1); ffma2(acc2[0][2], a0, w2); ffma2(acc2[0][3], a0, w3);
            ffma2(acc2[1][0], a1, w0); ffma2(acc2[1][1], a1, w1); ffma2(acc2[1][2], a1, w2); ffma2(acc2[1][3], a1, w3);
            ffma2(acc2[2][0], a2, w0); ffma2(acc2[2][1], a2, w1); ffma2(acc2[2][2], a2, w2); ffma2(acc2[2][3], a2, w3);
            ffma2(acc2[3][0], a3, w0); ffma2(acc2[3][1], a3, w1); ffma2(acc2[3][2], a3, w2); ffma2(acc2[3][3], a3, w3);
        }
#pragma unroll
        for (int a = 0; a < 4; a++) {
            ulonglong2* dst = reinterpret_cast<ulonglong2*>(&qs[(t0 + a) * 100 + oc]);
            dst[0] = make_ulonglong2(acc2[a][0], acc2[a][1]);
            dst[1] = make_ulonglong2(acc2[a][2], acc2[a][3]);
        }
    }
    __syncthreads();

    // ---- Phase C: banded attention, warp per slot ----
    int warp = tid >> 5, lane = tid & 31;
#pragma unroll
    for (int rep = 0; rep < 10; rep++) {
        int s = rep * 9 + warp;
        if (s < SLOTS) {
            int f = fb - 1 + s;
            if (f >= 0 && f < F_N) {
                float qv = qs[s * 100 + lane];
                float sc[3];
#pragma unroll
                for (int j = 0; j < 3; j++) {
                    float p = qv * qs[(s + j) * 100 + 32 + lane];
                    p += __shfl_xor_sync(0xffffffffu, p, 1);
                    p += __shfl_xor_sync(0xffffffffu, p, 2);
                    p += __shfl_xor_sync(0xffffffffu, p, 4);
                    sc[j] = (f + j < F_N) ? p * 0.35355339059327373f : -INFINITY;
                }
                float m = fmaxf(sc[0], fmaxf(sc[1], sc[2]));
                float e0 = __expf(sc[0] - m);
                float e1 = (f + 1 < F_N) ? __expf(sc[1] - m) : 0.f;
                float e2 = (f + 2 < F_N) ? __expf(sc[2] - m) : 0.f;
                float inv = 1.f / (e0 + e1 + e2);
                float ao = (e0 * qs[s * 100 + 64 + lane]
                          + e1 * qs[(s + 1) * 100 + 64 + lane]
                          + e2 * qs[(s + 2) * 100 + 64 + lane]) * inv;
                as_[s * 34 + lane] = ao;
            } else {
                as_[s * 34 + lane] = 0.f;
            }
        }
    }
    __syncthreads();

    // qs rows dead: overlay next-layer conv weights, or head params on the last layer
    if (!last) {
        for (int idx = tid; idx < 3072; idx += NTH) cw[idx] = cwn[idx];
    } else {
        for (int idx = tid; idx < 512; idx += NTH) cw[idx] = h1_w[idx];
        if (tid < 16) { cw[512 + tid] = h1_b[tid]; cw[528 + tid] = h2_w[tid]; }
        if (tid == 0) cw[544] = h2_b[0];
    }

    // ---- Phase D: prefetch conv-output, proj GEMM, BN/GELU, LN, writes; TOKEN-PAIR/thread ----
    {
        int p2 = tid >> 2;
        int o0 = (tid & 3) << 3;
        int sA = p2 * 2, sB = sA + 1;
        bool vp = p2 < 44;
        int fA_ = fb - 1 + sA;
        int fB_ = fA_ + 1;
        bool fvA = vp && (fA_ >= 0) && (fA_ < F_N);
        bool fvB = vp && (fB_ >= 0) && (fB_ < F_N);
        // prefetch gc_in with clamped addresses (overlaps the GEMM below)
        int fAc = min(max(fA_, 0), F_N - 1);
        int fBc = min(max(fB_, 0), F_N - 1);
        const float4* cgA = (const float4*)&gc_in[(rowbase + fAc) * 32 + o0];
        const float4* cgB = (const float4*)&gc_in[(rowbase + fBc) * 32 + o0];
        float4 cA0 = cgA[0], cA1 = cgA[1];
        float4 cB0 = cgB[0], cB1 = cgB[1];

        float yvA[8], yvB[8];
#pragma unroll
        for (int j = 0; j < 8; j++) { yvA[j] = 0.f; yvB[j] = 0.f; }
        if (vp) {
            u64 accA[4], accB[4];
            const u64* pb2 = (const u64*)(pb + o0);
#pragma unroll
            for (int k = 0; k < 4; k++) { accA[k] = pb2[k]; accB[k] = pb2[k]; }
            const u64* arA = (const u64*)(as_ + sA * 34);
            const u64* arB = (const u64*)(as_ + sB * 34);
#pragma unroll
            for (int i2 = 0; i2 < 16; i2++) {
                float2 fa = unpack2(arA[i2]);
                float2 fbv = unpack2(arB[i2]);
                u64 a0 = pack2(fa.x), a1 = pack2(fa.y);
                u64 b0 = pack2(fbv.x), b1 = pack2(fbv.y);
                const ulonglong2* w02 = (const ulonglong2*)(wp + (2 * i2) * 32 + o0);
                const ulonglong2* w12 = (const ulonglong2*)(wp + (2 * i2 + 1) * 32 + o0);
                ulonglong2 pq0 = w02[0], pq1 = w02[1];
                ulonglong2 pr0 = w12[0], pr1 = w12[1];
                u64 q0 = pq0.x, q1 = pq0.y, q2 = pq1.x, q3 = pq1.y;
                u64 r0 = pr0.x, r1 = pr0.y, r2 = pr1.x, r3 = pr1.y;
                ffma2(accA[0], a0, q0); ffma2(accA[1], a0, q1); ffma2(accA[2], a0, q2); ffma2(accA[3], a0, q3);
                ffma2(accA[0], a1, r0); ffma2(accA[1], a1, r1); ffma2(accA[2], a1, r2); ffma2(accA[3], a1, r3);
                ffma2(accB[0], b0, q0); ffma2(accB[1], b0, q1); ffma2(accB[2], b0, q2); ffma2(accB[3], b0, q3);
                ffma2(accB[0], b1, r0); ffma2(accB[1], b1, r1); ffma2(accB[2], b1, r2); ffma2(accB[3], b1, r3);
            }
            if (fvA) {
                float cv[8] = {cA0.x, cA0.y, cA0.z, cA0.w, cA1.x, cA1.y, cA1.z, cA1.w};
#pragma unroll
                for (int k = 0; k < 4; k++) {
                    float2 pa = unpack2(accA[k]);
                    float cn0 = cv[2 * k] * bna[o0 + 2 * k] + bnb[o0 + 2 * k];
                    float cn1 = cv[2 * k + 1] * bna[o0 + 2 * k + 1] + bnb[o0 + 2 * k + 1];
                    yvA[2 * k] = gelu_f(cn0) + pa.x;
                    yvA[2 * k + 1] = gelu_f(cn1) + pa.y;
                }
            }
            if (fvB) {
                float cv[8] = {cB0.x, cB0.y, cB0.z, cB0.w, cB1.x, cB1.y, cB1.z, cB1.w};
#pragma unroll
                for (int k = 0; k < 4; k++) {
                    float2 pa = unpack2(accB[k]);
                    float cn0 = cv[2 * k] * bna[o0 + 2 * k] + bnb[o0 + 2 * k];
                    float cn1 = cv[2 * k + 1] * bna[o0 + 2 * k + 1] + bnb[o0 + 2 * k + 1];
                    yvB[2 * k] = gelu_f(cn0) + pa.x;
                    yvB[2 * k + 1] = gelu_f(cn1) + pa.y;
                }
            }
        }
        // LayerNorm across the 4 threads of each token
        float lsA = 0.f, lqA = 0.f, lsB = 0.f, lqB = 0.f;
#pragma unroll
        for (int j = 0; j < 8; j++) {
            lsA += yvA[j]; lqA += yvA[j] * yvA[j];
            lsB += yvB[j]; lqB += yvB[j] * yvB[j];
        }
        lsA += __shfl_xor_sync(0xffffffffu, lsA, 1); lsA += __shfl_xor_sync(0xffffffffu, lsA, 2);
        lqA += __shfl_xor_sync(0xffffffffu, lqA, 1); lqA += __shfl_xor_sync(0xffffffffu, lqA, 2);
        lsB += __shfl_xor_sync(0xffffffffu, lsB, 1); lsB += __shfl_xor_sync(0xffffffffu, lsB, 2);
        lqB += __shfl_xor_sync(0xffffffffu, lqB, 1); lqB += __shfl_xor_sync(0xffffffffu, lqB, 2);
        float mA = lsA * (1.f / 32.f);
        float vA = lqA * (1.f / 32.f) - mA * mA;
        float rA = rsqrtf(vA + 1e-5f);
        float mB = lsB * (1.f / 32.f);
        float vB2 = lqB * (1.f / 32.f) - mB * mB;
        float rB = rsqrtf(vB2 + 1e-5f);
        if (vp) {
            float4* yoA = (float4*)&y[sA * 36 + o0];
            if (fvA) {
                float ov[8];
#pragma unroll
                for (int j = 0; j < 8; j++)
                    ov[j] = (yvA[j] - mA) * rA * lg[o0 + j] + lb[o0 + j];
                yoA[0] = make_float4(ov[0], ov[1], ov[2], ov[3]);
                yoA[1] = make_float4(ov[4], ov[5], ov[6], ov[7]);
                if (!last && sA >= 1 && sA <= E) {
                    float4* ho = (float4*)&hdst[(rowbase + fA_) * 32 + o0];
                    ho[0] = make_float4(ov[0], ov[1], ov[2], ov[3]);
                    ho[1] = make_float4(ov[4], ov[5], ov[6], ov[7]);
                }
            } else {
                yoA[0] = make_float4(0.f, 0.f, 0.f, 0.f);
                yoA[1] = make_float4(0.f, 0.f, 0.f, 0.f);
            }
            float4* yoB = (float4*)&y[sB * 36 + o0];
            if (fvB) {
                float ov[8];
#pragma unroll
                for (int j = 0; j < 8; j++)
                    ov[j] = (yvB[j] - mB) * rB * lg[o0 + j] + lb[o0 + j];
                yoB[0] = make_float4(ov[0], ov[1], ov[2], ov[3]);
                yoB[1] = make_float4(ov[4], ov[5], ov[6], ov[7]);
                if (!last && sB >= 1 && sB <= E) {
                    float4* ho = (float4*)&hdst[(rowbase + fB_) * 32 + o0];
                    ho[0] = make_float4(ov[0], ov[1], ov[2], ov[3]);
                    ho[1] = make_float4(ov[4], ov[5], ov[6], ov[7]);
                }
            } else {
                yoB[0] = make_float4(0.f, 0.f, 0.f, 0.f);
                yoB[1] = make_float4(0.f, 0.f, 0.f, 0.f);
            }
        }
    }
    __syncthreads();

    if (last) {
        // ---- Phase H: head from smem y, TWO threads per token (8 hidden units each) ----
        int t = tid >> 1, half = tid & 1;
        if (t < E) {
            int s = t + 1;
            int f = fb + t;
            float hv[32];
            const float4* yr4 = (const float4*)(y + s * 36);
#pragma unroll
            for (int k = 0; k < 8; k++) {
                float4 v = yr4[k];
                hv[4 * k] = v.x; hv[4 * k + 1] = v.y; hv[4 * k + 2] = v.z; hv[4 * k + 3] = v.w;
            }
            int j0 = half * 8;
            u64 s2[4];
            const u64* wb2 = (const u64*)(cw + 512 + j0);   // h1_b slice
#pragma unroll
            for (int k = 0; k < 4; k++) s2[k] = wb2[k];
#pragma unroll
            for (int i = 0; i < 32; i++) {
                u64 a2 = pack2(hv[i]);
                const u64* wr = (const u64*)(cw + i * 16 + j0);
#pragma unroll
                for (int k = 0; k < 4; k++) ffma2(s2[k], a2, wr[k]);
            }
            float m = (half == 0) ? cw[544] : 0.f;
            const float* ws2 = cw + 528 + j0;
#pragma unroll
            for (int k = 0; k < 4; k++) {
                float2 f2 = unpack2(s2[k]);
                m += gelu_f(f2.x) * ws2[2 * k] + gelu_f(f2.y) * ws2[2 * k + 1];
            }
            m += __shfl_xor_sync(0xffffffffu, m, 1);
            if (half == 0) out[rowbase + f] = 1.f / (1.f + expf(-m));
        }
        return;
    }

    // ---- fused next-layer conv on smem y ----
    conv_phase(y, cw, fb, E, rowbase, (int)blockIdx.y * NBX + blockIdx.x, R1, gc_out);
}

// ===== launcher =====
extern "C" void kernel_launch(void* const* d_in, const int* in_sizes, int n_in,
                              void* d_out, int out_size) {
    const float* x      = (const float*)d_in[0];
    const float* in_w   = (const float*)d_in[1];
    const float* in_b   = (const float*)d_in[2];
    const float* conv_w = (const float*)d_in[3];
    const float* bn_g   = (const float*)d_in[4];
    const float* bn_b   = (const float*)d_in[5];
    const float* qkv_w  = (const float*)d_in[6];
    const float* proj_w = (const float*)d_in[7];
    const float* proj_b = (const float*)d_in[8];
    const float* ln_g   = (const float*)d_in[9];
    const float* ln_b   = (const float*)d_in[10];
    const float* h1_w   = (const float*)d_in[11];
    const float* h1_b   = (const float*)d_in[12];
    const float* h2_w   = (const float*)d_in[13];
    const float* h2_b   = (const float*)d_in[14];
    float* out = (float*)d_out;

    cudaFuncSetAttribute(k_apply, cudaFuncAttributeMaxDynamicSharedMemorySize, SMEM_APPLY);

    dim3 grid(NBX, B_N);
    k_pre<<<grid, NTH>>>(x, in_w, in_b, conv_w);
    for (int l = 0; l < 4; l++) {
        int src = l & 1;
        int cidx = l & 1;   // layer l reads g_c[l&1], writes g_c[(l&1)^1]
        int last = (l == 3) ? 1 : 0;
        k_bnfin<<<32, 256>>>(bn_g + l * 32, bn_b + l * 32);
        k_apply<<<grid, NTH, SMEM_APPLY>>>(qkv_w + l * 3072, proj_w + l * 1024,
                                           proj_b + l * 32, ln_g + l * 32, ln_b + l * 32,
                                           conv_w + (l + 1 < 4 ? l + 1 : 0) * 3072,
                                           h1_w, h1_b, h2_w, h2_b, out,
                                           src, cidx, last);
    }
}